// round 15
// baseline (speedup 1.0000x reference)
#include <cuda_runtime.h>
#include <cstdint>

// out[b,t,a] = start_state[b,a] + (t/255) * patterns[iid[b], t, a]
// B=256, T=256, AD=64 -> each (b,t) row = 64 floats = 8 x 256-bit vectors.
//
// FINAL (converged). 1024 CTAs x 256 threads; each thread: 2 front-batched
// 256-bit loads (LDG.E.256) + 2 256-bit stores (STG.E.256); iid/start_state
// amortized; fully coalesced (warp = 4 contiguous 256B rows).
//
// Search record (14 rounds): warp-LDG v4 MLP{1,4,8}, +/- streaming-store
// hints, TMA bulk load, 4-deep TMA pipeline, TMA bulk store, cp.async
// (LDGSTS), v8x{2,4,8}, TPB{128,256}, hybrid grids. All sit on a
// memory-latency + fixed-replay-overhead floor (no pipe >25% in any
// variant); this shape is the reproducible minimum: wall 8.64-8.67us
// (3 consecutive runs within one 32ns timer tick), ncu 7.6-7.8us.

#define B_   256
#define T_   256
#define AD_  64
#define TPB  256

struct f8 { float v[8]; };

__device__ __forceinline__ f8 ldg_v8(const float* p) {
    f8 r;
    asm volatile("ld.global.nc.v8.f32 {%0,%1,%2,%3,%4,%5,%6,%7}, [%8];"
                 : "=f"(r.v[0]), "=f"(r.v[1]), "=f"(r.v[2]), "=f"(r.v[3]),
                   "=f"(r.v[4]), "=f"(r.v[5]), "=f"(r.v[6]), "=f"(r.v[7])
                 : "l"(p));
    return r;
}

__device__ __forceinline__ void stg_v8(float* p, const f8& r) {
    asm volatile("st.global.v8.f32 [%0], {%1,%2,%3,%4,%5,%6,%7,%8};"
                 :: "l"(p),
                    "f"(r.v[0]), "f"(r.v[1]), "f"(r.v[2]), "f"(r.v[3]),
                    "f"(r.v[4]), "f"(r.v[5]), "f"(r.v[6]), "f"(r.v[7])
                 : "memory");
}

__global__ __launch_bounds__(TPB)
void traj_kernel(const float* __restrict__ start_state,    // [B, 64]
                 const int*   __restrict__ instruction_id, // [B]
                 const float* __restrict__ patterns,       // [V, T, 64]
                 float*       __restrict__ out)            // [B, T, 64]
{
    const unsigned bid   = blockIdx.x;
    const unsigned b     = bid >> 2;          // 4 chunks of 64 t per batch row
    const unsigned chunk = bid & 3u;
    const unsigned tid   = threadIdx.x;
    const unsigned a8    = tid & 7u;          // 256-bit slot within 64-float row
    const unsigned trow  = tid >> 3;          // 0..31
    const unsigned tbase = chunk * 64u;

    const int iid = __ldg(&instruction_id[b]);

    const f8 s = ldg_v8(start_state + (size_t)b * AD_ + a8 * 8u);

    const float* __restrict__ pat =
        patterns + ((size_t)iid * T_ + tbase) * AD_ + a8 * 8u;
    float* __restrict__ dst =
        out + ((size_t)b * T_ + tbase) * AD_ + a8 * 8u;

    // 2 independent 256-bit loads, front-batched.
    const unsigned t0 = trow;          // local t, iter 0
    const unsigned t1 = trow + 32u;    // local t, iter 1
    f8 p0 = ldg_v8(pat + (size_t)t0 * AD_);
    f8 p1 = ldg_v8(pat + (size_t)t1 * AD_);

    const float prog0 = (float)(tbase + t0) * (1.0f / (float)(T_ - 1));
    const float prog1 = (float)(tbase + t1) * (1.0f / (float)(T_ - 1));

    f8 r0, r1;
#pragma unroll
    for (int i = 0; i < 8; i++) r0.v[i] = fmaf(prog0, p0.v[i], s.v[i]);
#pragma unroll
    for (int i = 0; i < 8; i++) r1.v[i] = fmaf(prog1, p1.v[i], s.v[i]);

    stg_v8(dst + (size_t)t0 * AD_, r0);
    stg_v8(dst + (size_t)t1 * AD_, r1);
}

extern "C" void kernel_launch(void* const* d_in, const int* in_sizes, int n_in,
                              void* d_out, int out_size)
{
    const float* start_state    = (const float*)d_in[0];
    const int*   instruction_id = (const int*)  d_in[1];
    const float* patterns       = (const float*)d_in[27];
    float*       out            = (float*)d_out;

    traj_kernel<<<B_ * 4, TPB>>>(start_state, instruction_id, patterns, out);
}

// round 16
// speedup vs baseline: 1.0074x; 1.0074x over previous
#include <cuda_runtime.h>
#include <cstdint>

// out[b,t,a] = start_state[b,a] + (t/255) * patterns[iid[b], t, a]
// B=256, T=256, AD=64 -> each (b,t) row = 64 floats = 8 x 256-bit vectors.
//
// R16: FINAL shape (v8x2, 1024 CTAs x 256 thr) with CHUNK-MAJOR CTA order:
// consecutive CTAs process different batch rows (b = bid & 255), so the
// first wave touches all 256 distinct pattern rows -> uniform LTS-slice /
// die spread from cycle 0 instead of concentrating on ~37 rows.
// Everything else identical to the measured-minimum kernel
// (wall 8.64-8.70us over 3 runs, ncu 7.6-7.8us, 13-variant search record).

#define B_   256
#define T_   256
#define AD_  64
#define TPB  256

struct f8 { float v[8]; };

__device__ __forceinline__ f8 ldg_v8(const float* p) {
    f8 r;
    asm volatile("ld.global.nc.v8.f32 {%0,%1,%2,%3,%4,%5,%6,%7}, [%8];"
                 : "=f"(r.v[0]), "=f"(r.v[1]), "=f"(r.v[2]), "=f"(r.v[3]),
                   "=f"(r.v[4]), "=f"(r.v[5]), "=f"(r.v[6]), "=f"(r.v[7])
                 : "l"(p));
    return r;
}

__device__ __forceinline__ void stg_v8(float* p, const f8& r) {
    asm volatile("st.global.v8.f32 [%0], {%1,%2,%3,%4,%5,%6,%7,%8};"
                 :: "l"(p),
                    "f"(r.v[0]), "f"(r.v[1]), "f"(r.v[2]), "f"(r.v[3]),
                    "f"(r.v[4]), "f"(r.v[5]), "f"(r.v[6]), "f"(r.v[7])
                 : "memory");
}

__global__ __launch_bounds__(TPB)
void traj_kernel(const float* __restrict__ start_state,    // [B, 64]
                 const int*   __restrict__ instruction_id, // [B]
                 const float* __restrict__ patterns,       // [V, T, 64]
                 float*       __restrict__ out)            // [B, T, 64]
{
    const unsigned bid   = blockIdx.x;
    const unsigned b     = bid & 255u;        // chunk-major: adjacent CTAs -> different b
    const unsigned chunk = bid >> 8;          // 0..3
    const unsigned tid   = threadIdx.x;
    const unsigned a8    = tid & 7u;          // 256-bit slot within 64-float row
    const unsigned trow  = tid >> 3;          // 0..31
    const unsigned tbase = chunk * 64u;

    const int iid = __ldg(&instruction_id[b]);

    const f8 s = ldg_v8(start_state + (size_t)b * AD_ + a8 * 8u);

    const float* __restrict__ pat =
        patterns + ((size_t)iid * T_ + tbase) * AD_ + a8 * 8u;
    float* __restrict__ dst =
        out + ((size_t)b * T_ + tbase) * AD_ + a8 * 8u;

    // 2 independent 256-bit loads, front-batched.
    const unsigned t0 = trow;          // local t, iter 0
    const unsigned t1 = trow + 32u;    // local t, iter 1
    f8 p0 = ldg_v8(pat + (size_t)t0 * AD_);
    f8 p1 = ldg_v8(pat + (size_t)t1 * AD_);

    const float prog0 = (float)(tbase + t0) * (1.0f / (float)(T_ - 1));
    const float prog1 = (float)(tbase + t1) * (1.0f / (float)(T_ - 1));

    f8 r0, r1;
#pragma unroll
    for (int i = 0; i < 8; i++) r0.v[i] = fmaf(prog0, p0.v[i], s.v[i]);
#pragma unroll
    for (int i = 0; i < 8; i++) r1.v[i] = fmaf(prog1, p1.v[i], s.v[i]);

    stg_v8(dst + (size_t)t0 * AD_, r0);
    stg_v8(dst + (size_t)t1 * AD_, r1);
}

extern "C" void kernel_launch(void* const* d_in, const int* in_sizes, int n_in,
                              void* d_out, int out_size)
{
    const float* start_state    = (const float*)d_in[0];
    const int*   instruction_id = (const int*)  d_in[1];
    const float* patterns       = (const float*)d_in[27];
    float*       out            = (float*)d_out;

    traj_kernel<<<B_ * 4, TPB>>>(start_state, instruction_id, patterns, out);
}